// round 5
// baseline (speedup 1.0000x reference)
#include <cuda_runtime.h>
#include <cuda_bf16.h>
#include <math.h>

#define NB    32
#define HID   1024
#define TSTEP 63
#define ENCL  64
#define G3    3072

#define DEC_HIDS_ELEMS (NB * TSTEP * HID)
#define ATTS_ELEMS     (NB * ENCL * TSTEP)
#define ATT_BASE       DEC_HIDS_ELEMS
#define DECPREV_BASE   (DEC_HIDS_ELEMS + ATTS_ELEMS)

// ---------------------------------------------------------------------------
// Scratch globals
// ---------------------------------------------------------------------------
__device__ float gt_dec[1024 * 1024];   // W_att_dec^T [k][j]
__device__ float gt_ctx[1024 * 1024];
__device__ float gt_hh0[1024 * G3];
__device__ float gt_hh1[1024 * G3];
__device__ float gt_ih0[1024 * G3];
__device__ float gt_ih1[1024 * G3];

__device__ float g_enc_proj[NB * ENCL * 1024];
__device__ float g_emb_merged[TSTEP * NB * 1024];

__device__ float g_h[2 * NB * HID];
__device__ float g_ctx[NB * HID];

__device__ float g_dp_part [8 * NB * HID];
__device__ float g_gh0_part[8 * NB * G3];
__device__ float g_gh1_part[8 * NB * G3];
__device__ float g_mg_part [8 * NB * HID];
__device__ float g_gi_part [8 * NB * G3];

__device__ __forceinline__ float tanh_fast(float x) {
    float y;
    asm("tanh.approx.f32 %0, %1;" : "=f"(y) : "f"(x));
    return y;
}

__device__ __forceinline__ void cp16(void* smem_dst, const void* gsrc) {
    unsigned s = (unsigned)__cvta_generic_to_shared(smem_dst);
    asm volatile("cp.async.ca.shared.global [%0], [%1], 16;" :: "r"(s), "l"(gsrc));
}
__device__ __forceinline__ void cp_commit() {
    asm volatile("cp.async.commit_group;");
}
template<int N> __device__ __forceinline__ void cp_wait() {
    asm volatile("cp.async.wait_group %0;" :: "n"(N));
}

__global__ void init_h_kernel(const float* __restrict__ dec_init) {
    int i = blockIdx.x * 256 + threadIdx.x;
    g_h[i] = dec_init[i];
}

// ---------------------------------------------------------------------------
// Weight transpose: W[r][k] -> Wt[k][r]  (k inner = 1024 on all)
// ---------------------------------------------------------------------------
__global__ void transpose_kernel(const float* __restrict__ W_att_dec,
                                 const float* __restrict__ W_ctx,
                                 const float* __restrict__ W_hh,
                                 const float* __restrict__ W_ih) {
    __shared__ float s[32][33];
    int b = blockIdx.x;
    const float* in; float* out; int R, loc;
    if (b < 1024)       { in = W_att_dec;        out = gt_dec; R = 1024; loc = b; }
    else if (b < 2048)  { in = W_ctx;            out = gt_ctx; R = 1024; loc = b - 1024; }
    else if (b < 5120)  { in = W_hh;             out = gt_hh0; R = G3;   loc = b - 2048; }
    else if (b < 8192)  { in = W_hh + G3 * 1024; out = gt_hh1; R = G3;   loc = b - 5120; }
    else if (b < 11264) { in = W_ih;             out = gt_ih0; R = G3;   loc = b - 8192; }
    else                { in = W_ih + G3 * 1024; out = gt_ih1; R = G3;   loc = b - 11264; }
    int tr = loc >> 5;     // row-tile over R
    int tk = loc & 31;     // k-tile over 1024
    int x = threadIdx.x & 31, y = threadIdx.x >> 5;
#pragma unroll
    for (int i = 0; i < 4; i++) {
        int r = tr * 32 + y + i * 8;
        s[y + i * 8][x] = in[(size_t)r * 1024 + tk * 32 + x];
    }
    __syncthreads();
#pragma unroll
    for (int i = 0; i < 4; i++) {
        int k = tk * 32 + y + i * 8;
        out[(size_t)k * R + tr * 32 + x] = s[x][y + i * 8];
    }
}

// ---------------------------------------------------------------------------
// GEMM v2 core: out[32n x 128j] += A[32 x 128k-slice] @ Wt[k][j]
// 128 threads; 8n x 4j per thread; As loaded once; Ws cp.async double-buffered.
// amode 0: A given; amode 1: A = emb_merged[t] + 8 mg partials
// ---------------------------------------------------------------------------
__device__ __forceinline__ void gemm2(const float* __restrict__ A,
                                      const float* __restrict__ Wt,
                                      int C, int j0, int k0,
                                      float* __restrict__ outp,
                                      int amode, int t) {
    __shared__ float As[128 * 32];       // [k][n], stride 32 (reads are broadcast)
    __shared__ float Ws[2][32 * 128];    // [k][j]
    int tid = threadIdx.x;
    int tx = tid & 31, ty = tid >> 5;

    // issue Ws chunks 0 and 1
#pragma unroll
    for (int cc = 0; cc < 2; cc++) {
        for (int i = tid; i < 1024; i += 128) {
            int k = i >> 5, jq = i & 31;
            cp16(&Ws[cc][k * 128 + jq * 4],
                 Wt + (size_t)(k0 + cc * 32 + k) * C + j0 + jq * 4);
        }
        cp_commit();
    }

    // stage As once (transpose 32n x 128k -> [k][n])
    {
        int n = tid >> 2, kq = tid & 3;
#pragma unroll
        for (int p = 0; p < 8; p++) {
            int kl = (kq + p * 4) * 4;
            float4 v;
            if (amode == 0) {
                v = *(const float4*)(A + (size_t)n * 1024 + k0 + kl);
            } else {
                v = *(const float4*)(g_emb_merged + ((size_t)t * NB + n) * 1024 + k0 + kl);
#pragma unroll
                for (int s = 0; s < 8; s++) {
                    float4 pv = *(const float4*)(g_mg_part + ((size_t)s * NB + n) * 1024 + k0 + kl);
                    v.x += pv.x; v.y += pv.y; v.z += pv.z; v.w += pv.w;
                }
            }
            As[(kl + 0) * 32 + n] = v.x;
            As[(kl + 1) * 32 + n] = v.y;
            As[(kl + 2) * 32 + n] = v.z;
            As[(kl + 3) * 32 + n] = v.w;
        }
    }

    float acc[8][4];
#pragma unroll
    for (int i = 0; i < 8; i++)
#pragma unroll
        for (int j = 0; j < 4; j++) acc[i][j] = 0.f;

#pragma unroll
    for (int c = 0; c < 4; c++) {
        if (c == 3) cp_wait<0>(); else cp_wait<1>();
        __syncthreads();
        const float* ws = Ws[c & 1];
        const float* as = As + c * 32 * 32;
#pragma unroll
        for (int kk = 0; kk < 32; kk++) {
            float4 a0 = *(const float4*)(as + kk * 32 + ty * 8);
            float4 a1 = *(const float4*)(as + kk * 32 + ty * 8 + 4);
            float4 w  = *(const float4*)(ws + kk * 128 + tx * 4);
            float av[8] = {a0.x, a0.y, a0.z, a0.w, a1.x, a1.y, a1.z, a1.w};
#pragma unroll
            for (int i = 0; i < 8; i++) {
                acc[i][0] += av[i] * w.x;
                acc[i][1] += av[i] * w.y;
                acc[i][2] += av[i] * w.z;
                acc[i][3] += av[i] * w.w;
            }
        }
        if (c < 2) {
            __syncthreads();   // buffer c&1 free to overwrite
            for (int i = tid; i < 1024; i += 128) {
                int k = i >> 5, jq = i & 31;
                cp16(&Ws[c & 1][k * 128 + jq * 4],
                     Wt + (size_t)(k0 + (c + 2) * 32 + k) * C + j0 + jq * 4);
            }
            cp_commit();
        }
    }
#pragma unroll
    for (int i = 0; i < 8; i++) {
        int n = ty * 8 + i;
        float4 r = {acc[i][0], acc[i][1], acc[i][2], acc[i][3]};
        *(float4*)(outp + (size_t)n * C + j0 + tx * 4) = r;
    }
}

// phase A: dec_proj (8 tiles x8 splits) + gh0 (24x8) + gh1 (24x8) = 448 blocks
__global__ void __launch_bounds__(128) phaseA_kernel() {
    int b = blockIdx.x;
    if (b < 64) {
        int tile = b >> 3, split = b & 7;
        gemm2(g_h + NB * HID, gt_dec, 1024, tile * 128, split * 128,
              g_dp_part + (size_t)split * NB * 1024, 0, 0);
    } else if (b < 256) {
        int x = b - 64; int tile = x >> 3, split = x & 7;
        gemm2(g_h, gt_hh0, G3, tile * 128, split * 128,
              g_gh0_part + (size_t)split * NB * G3, 0, 0);
    } else {
        int x = b - 256; int tile = x >> 3, split = x & 7;
        gemm2(g_h + NB * HID, gt_hh1, G3, tile * 128, split * 128,
              g_gh1_part + (size_t)split * NB * G3, 0, 0);
    }
}

// merged: ctx @ W_ctx^T : 8 tiles x 8 splits = 64 blocks
__global__ void __launch_bounds__(128) merged_kernel() {
    int tile = blockIdx.x >> 3, split = blockIdx.x & 7;
    gemm2(g_ctx, gt_ctx, 1024, tile * 128, split * 128,
          g_mg_part + (size_t)split * NB * 1024, 0, 0);
}

// gi: 24 tiles x 8 splits = 192 blocks
__global__ void __launch_bounds__(128) gi_kernel(int layer, int t) {
    int tile = blockIdx.x >> 3, split = blockIdx.x & 7;
    if (layer == 0)
        gemm2(nullptr, gt_ih0, G3, tile * 128, split * 128,
              g_gi_part + (size_t)split * NB * G3, 1, t);
    else
        gemm2(g_h, gt_ih1, G3, tile * 128, split * 128,
              g_gi_part + (size_t)split * NB * G3, 0, 0);
}

// ---------------------------------------------------------------------------
// Prologue GEMM (64x64 tiles, K=1024), double-buffered (original W layout)
// ---------------------------------------------------------------------------
__global__ void prol_gemm_kernel(int mode,
                                 const float* __restrict__ enc_hids,
                                 const int*   __restrict__ input_ids,
                                 const float* __restrict__ emb_table,
                                 const float* __restrict__ b_in,
                                 const float* __restrict__ b_ctx,
                                 const float* __restrict__ W) {
    __shared__ float As[2][32 * 68];
    __shared__ float Ws[2][32 * 68];
    int b = blockIdx.x;
    int rt = b >> 4, ct = b & 15;
    int r0 = rt * 64, c0 = ct * 64;
    int tid = threadIdx.x;
    int lp = tid & 7, lr = tid >> 3;
    int tx = tid & 15, ty = tid >> 4;
    int rows = (mode == 0) ? 2048 : (TSTEP * NB);

    float4 a[2], wv[2];
#define PROL_FETCH(k0)                                                          \
    {                                                                           \
        _Pragma("unroll")                                                       \
        for (int h = 0; h < 2; h++) {                                           \
            int gr = r0 + lr + h * 32;                                          \
            if (mode == 0) {                                                    \
                a[h] = *(const float4*)(enc_hids + (size_t)gr * 1024 + (k0) + lp * 4); \
            } else if (gr < rows) {                                             \
                int id = input_ids[(gr & 31) * 64 + (gr >> 5)];                 \
                a[h] = *(const float4*)(emb_table + (size_t)id * 1024 + (k0) + lp * 4); \
            } else {                                                            \
                a[h] = make_float4(0.f, 0.f, 0.f, 0.f);                         \
            }                                                                   \
            wv[h] = *(const float4*)(W + (size_t)(c0 + lr + h * 32) * 1024 + (k0) + lp * 4); \
        }                                                                       \
    }
#define PROL_STORE(buf)                                                         \
    {                                                                           \
        _Pragma("unroll")                                                       \
        for (int h = 0; h < 2; h++) {                                           \
            int r = lr + h * 32;                                                \
            As[buf][(lp * 4 + 0) * 68 + r] = a[h].x;                            \
            As[buf][(lp * 4 + 1) * 68 + r] = a[h].y;                            \
            As[buf][(lp * 4 + 2) * 68 + r] = a[h].z;                            \
            As[buf][(lp * 4 + 3) * 68 + r] = a[h].w;                            \
            Ws[buf][(lp * 4 + 0) * 68 + r] = wv[h].x;                           \
            Ws[buf][(lp * 4 + 1) * 68 + r] = wv[h].y;                           \
            Ws[buf][(lp * 4 + 2) * 68 + r] = wv[h].z;                           \
            Ws[buf][(lp * 4 + 3) * 68 + r] = wv[h].w;                           \
        }                                                                       \
    }

    float acc[4][4];
#pragma unroll
    for (int i = 0; i < 4; i++)
#pragma unroll
        for (int j = 0; j < 4; j++) acc[i][j] = 0.f;

    PROL_FETCH(0);
    PROL_STORE(0);
    __syncthreads();
    for (int c = 0; c < 32; c++) {
        const float* as = As[c & 1];
        const float* ws = Ws[c & 1];
        if (c + 1 < 32) PROL_FETCH((c + 1) * 32);
#pragma unroll
        for (int kk = 0; kk < 32; kk++) {
            float4 a4 = *(const float4*)&as[kk * 68 + ty * 4];
            float4 b4 = *(const float4*)&ws[kk * 68 + tx * 4];
            float avv[4] = {a4.x, a4.y, a4.z, a4.w};
            float bvv[4] = {b4.x, b4.y, b4.z, b4.w};
#pragma unroll
            for (int i = 0; i < 4; i++)
#pragma unroll
                for (int j = 0; j < 4; j++) acc[i][j] += avv[i] * bvv[j];
        }
        if (c + 1 < 32) {
            PROL_STORE((c + 1) & 1);
            __syncthreads();
        }
    }
    float* outb = (mode == 0) ? g_enc_proj : g_emb_merged;
#pragma unroll
    for (int i = 0; i < 4; i++) {
        int r = r0 + ty * 4 + i;
        if (r >= rows) continue;
#pragma unroll
        for (int j = 0; j < 4; j++) {
            int c = c0 + tx * 4 + j;
            float bias = (mode == 1) ? (b_in[c] + b_ctx[c]) : 0.f;
            outb[(size_t)r * 1024 + c] = acc[i][j] + bias;
        }
    }
#undef PROL_FETCH
#undef PROL_STORE
}

// ---------------------------------------------------------------------------
// Fused attention: scores (tanh) + softmax + atts out + ctx. 32 blocks x 256
// ---------------------------------------------------------------------------
__global__ void attn_kernel(const float* __restrict__ enc_hids,
                            const float* __restrict__ v_att,
                            float* __restrict__ out, int t) {
    __shared__ float sdec[1024];
    __shared__ float sv[1024];
    __shared__ float sscore[64];
    __shared__ float satt[64];
    int n = blockIdx.x, tid = threadIdx.x;
    for (int i = tid; i < 1024; i += 256) {
        float s = 0.f;
#pragma unroll
        for (int sp = 0; sp < 8; sp++)
            s += g_dp_part[((size_t)sp * NB + n) * 1024 + i];
        sdec[i] = s;
        sv[i] = v_att[i];
    }
    __syncthreads();
    int w = tid >> 5, lane = tid & 31;
#pragma unroll
    for (int li = 0; li < 8; li++) {
        int l = w * 8 + li;
        const float* ep = g_enc_proj + ((size_t)n * 64 + l) * 1024;
        float s = 0.f;
        for (int a = lane; a < 1024; a += 32)
            s += tanh_fast(ep[a] + sdec[a]) * sv[a];
#pragma unroll
        for (int o = 16; o; o >>= 1) s += __shfl_xor_sync(0xffffffffu, s, o);
        if (lane == 0) sscore[l] = s;
    }
    __syncthreads();
    if (tid < 32) {
        float a0 = sscore[tid], a1 = sscore[tid + 32];
        float m = fmaxf(a0, a1);
#pragma unroll
        for (int o = 16; o; o >>= 1) m = fmaxf(m, __shfl_xor_sync(0xffffffffu, m, o));
        float e0 = __expf(a0 - m), e1 = __expf(a1 - m);
        float sum = e0 + e1;
#pragma unroll
        for (int o = 16; o; o >>= 1) sum += __shfl_xor_sync(0xffffffffu, sum, o);
        float inv = 1.f / sum;
        satt[tid]      = e0 * inv;
        satt[tid + 32] = e1 * inv;
        out[ATT_BASE + ((size_t)n * 64 + tid)      * TSTEP + t] = e0 * inv;
        out[ATT_BASE + ((size_t)n * 64 + tid + 32) * TSTEP + t] = e1 * inv;
    }
    __syncthreads();
    int d = tid * 4;
    float4 acc = {0.f, 0.f, 0.f, 0.f};
    const float* eh = enc_hids + (size_t)n * 64 * 1024 + d;
#pragma unroll 8
    for (int l = 0; l < 64; l++) {
        float  al = satt[l];
        float4 e  = *(const float4*)(eh + (size_t)l * 1024);
        acc.x += al * e.x; acc.y += al * e.y; acc.z += al * e.z; acc.w += al * e.w;
    }
    *(float4*)&g_ctx[n * 1024 + d] = acc;
}

// ---------------------------------------------------------------------------
// GRU combine: 8 gi + 8 gh partials + biases
// ---------------------------------------------------------------------------
__device__ __forceinline__ void add4(float* a, float4 v) {
    a[0] += v.x; a[1] += v.y; a[2] += v.z; a[3] += v.w;
}

__global__ void combine_kernel(int layer, int t,
                               const float* __restrict__ b_ih_l,
                               const float* __restrict__ b_hh_l,
                               float* __restrict__ out_hid) {
    int n = blockIdx.x;
    int j = threadIdx.x * 4;
    const float* ghp = layer ? g_gh1_part : g_gh0_part;
    float* h = g_h + (size_t)layer * NB * HID + n * HID;

    float gi[3][4] = {}, gh[3][4] = {};
#pragma unroll
    for (int g = 0; g < 3; g++) {
#pragma unroll
        for (int s = 0; s < 8; s++) {
            add4(gi[g], *(const float4*)(g_gi_part + ((size_t)s * NB + n) * G3 + g * 1024 + j));
            add4(gh[g], *(const float4*)(ghp       + ((size_t)s * NB + n) * G3 + g * 1024 + j));
        }
        add4(gi[g], *(const float4*)(b_ih_l + g * 1024 + j));
        add4(gh[g], *(const float4*)(b_hh_l + g * 1024 + j));
    }
    float4 ho = *(const float4*)(h + j);
    float ho_[4] = {ho.x, ho.y, ho.z, ho.w};
    float hn_[4];
#pragma unroll
    for (int c = 0; c < 4; c++) {
        float r  = 1.f / (1.f + expf(-(gi[0][c] + gh[0][c])));
        float z  = 1.f / (1.f + expf(-(gi[1][c] + gh[1][c])));
        float nn = tanhf(gi[2][c] + r * gh[2][c]);
        hn_[c] = (1.f - z) * nn + z * ho_[c];
    }
    float4 hv = {hn_[0], hn_[1], hn_[2], hn_[3]};
    *(float4*)(h + j) = hv;
    if (out_hid)
        *(float4*)(out_hid + ((size_t)n * TSTEP + t) * 1024 + j) = hv;
}

__global__ void copy_hfinal_kernel(float* __restrict__ out) {
    int i = blockIdx.x * 256 + threadIdx.x;
    out[DECPREV_BASE + i] = g_h[i];
}

// ---------------------------------------------------------------------------
extern "C" void kernel_launch(void* const* d_in, const int* in_sizes, int n_in,
                              void* d_out, int out_size) {
    const int*   input_ids = (const int*)  d_in[0];
    const float* dec_init  = (const float*)d_in[1];
    const float* enc_hids  = (const float*)d_in[2];
    const float* emb_table = (const float*)d_in[3];
    const float* W_in      = (const float*)d_in[4];
    const float* b_in      = (const float*)d_in[5];
    const float* W_ctx     = (const float*)d_in[6];
    const float* b_ctx     = (const float*)d_in[7];
    const float* W_att_dec = (const float*)d_in[8];
    const float* W_att_enc = (const float*)d_in[9];
    const float* v_att     = (const float*)d_in[10];
    const float* W_ih      = (const float*)d_in[11];
    const float* W_hh      = (const float*)d_in[12];
    const float* b_ih      = (const float*)d_in[13];
    const float* b_hh      = (const float*)d_in[14];
    float* out = (float*)d_out;

    init_h_kernel<<<256, 256>>>(dec_init);
    transpose_kernel<<<14336, 256>>>(W_att_dec, W_ctx, W_hh, W_ih);
    prol_gemm_kernel<<<512, 256>>>(0, enc_hids, input_ids, emb_table, b_in, b_ctx, W_att_enc);
    prol_gemm_kernel<<<512, 256>>>(1, enc_hids, input_ids, emb_table, b_in, b_ctx, W_in);

    for (int t = 0; t < TSTEP; t++) {
        phaseA_kernel<<<448, 128>>>();
        attn_kernel<<<32, 256>>>(enc_hids, v_att, out, t);
        merged_kernel<<<64, 128>>>();
        gi_kernel<<<192, 128>>>(0, t);
        combine_kernel<<<32, 256>>>(0, t, b_ih, b_hh, nullptr);
        gi_kernel<<<192, 128>>>(1, t);
        combine_kernel<<<32, 256>>>(1, t, b_ih + G3, b_hh + G3, out);
    }
    copy_hfinal_kernel<<<256, 256>>>(out);
}

// round 7
// speedup vs baseline: 1.6011x; 1.6011x over previous
#include <cuda_runtime.h>
#include <cuda_bf16.h>
#include <math.h>
#include <stdint.h>

#define NB    32
#define HID   1024
#define TSTEP 63
#define ENCL  64
#define G3    3072
#define PADK  36

#define DEC_HIDS_ELEMS (NB * TSTEP * HID)
#define ATTS_ELEMS     (NB * ENCL * TSTEP)
#define ATT_BASE       DEC_HIDS_ELEMS
#define DECPREV_BASE   (DEC_HIDS_ELEMS + ATTS_ELEMS)

// ---------------------------------------------------------------------------
// Scratch
// ---------------------------------------------------------------------------
__device__ float g_enc_proj[NB * ENCL * 1024];
__device__ float g_emb_merged[TSTEP * NB * 1024];

__device__ float g_h[2 * NB * HID];
__device__ float g_ctx[NB * HID];
__device__ float g_merged[NB * HID];

__device__ float g_dp_part [4 * NB * HID];
__device__ float g_gh0_part[4 * NB * G3];
__device__ float g_gh1_part[4 * NB * G3];
__device__ float g_gi_part [4 * NB * G3];

__device__ __forceinline__ float tanh_fast(float x) {
    float y;
    asm("tanh.approx.f32 %0, %1;" : "=f"(y) : "f"(x));
    return y;
}
__device__ __forceinline__ uint32_t f2tf(float x) {
    uint32_t r;
    asm("cvt.rna.tf32.f32 %0, %1;" : "=r"(r) : "f"(x));
    return r;
}
__device__ __forceinline__ void mma8(float* d, const uint32_t* a,
                                     uint32_t b0, uint32_t b1) {
    asm volatile(
        "mma.sync.aligned.m16n8k8.row.col.f32.tf32.tf32.f32 "
        "{%0,%1,%2,%3}, {%4,%5,%6,%7}, {%8,%9}, {%0,%1,%2,%3};"
        : "+f"(d[0]), "+f"(d[1]), "+f"(d[2]), "+f"(d[3])
        : "r"(a[0]), "r"(a[1]), "r"(a[2]), "r"(a[3]), "r"(b0), "r"(b1));
}
__device__ __forceinline__ void cp16(void* smem_dst, const void* gsrc) {
    unsigned s = (unsigned)__cvta_generic_to_shared(smem_dst);
    asm volatile("cp.async.ca.shared.global [%0], [%1], 16;" :: "r"(s), "l"(gsrc));
}
__device__ __forceinline__ void cp_commit() {
    asm volatile("cp.async.commit_group;");
}
template<int N> __device__ __forceinline__ void cp_wait() {
    asm volatile("cp.async.wait_group %0;" :: "n"(N));
}

__global__ void init_h_kernel(const float* __restrict__ dec_init) {
    int i = blockIdx.x * 256 + threadIdx.x;
    g_h[i] = dec_init[i];
}

// ---------------------------------------------------------------------------
// tf32 tensor-core GEMM: out[32 x (NT*32)cols @j0] = A[32 x KR@k0] @ W^T
// A: [32][1024] fp32 row-major.  W: [C][1024] fp32 (native layout = .col B).
// 128 threads / 4 warps; warp covers NT*8 cols; chunk = 32 k, double buffered.
// ---------------------------------------------------------------------------
__device__ __forceinline__ void stage_chunk(float* Asb, float* Wsb,
                                            const float* __restrict__ A,
                                            const float* __restrict__ W,
                                            int j0, int kg, int nt2, int tid) {
#pragma unroll
    for (int i = 0; i < 2; i++) {
        int idx = tid + i * 128;
        int row = idx >> 3, seg = idx & 7;
        cp16(Asb + row * PADK + seg * 4, A + (size_t)row * 1024 + kg + seg * 4);
    }
    for (int i = 0; i < nt2; i++) {
        int idx = tid + i * 128;
        int row = idx >> 3, seg = idx & 7;
        cp16(Wsb + row * PADK + seg * 4, W + (size_t)(j0 + row) * 1024 + kg + seg * 4);
    }
    cp_commit();
}

template<int NT, int NCH>
__device__ __forceinline__ void gemm_tc(const float* __restrict__ A,
                                        const float* __restrict__ W,
                                        int C, int j0, int k0,
                                        float* __restrict__ outp,
                                        const float* __restrict__ addend) {
    __shared__ float As[2][32 * PADK];
    __shared__ float Ws[2][128 * PADK];
    int tid = threadIdx.x;
    int wid = tid >> 5, lane = tid & 31;
    int r = lane >> 2, q = lane & 3;

    stage_chunk(As[0], Ws[0], A, W, j0, k0, NT * 2, tid);
    stage_chunk(As[1], Ws[1], A, W, j0, k0 + 32, NT * 2, tid);

    float acc[2][NT][4];
#pragma unroll
    for (int mt = 0; mt < 2; mt++)
#pragma unroll
        for (int nt = 0; nt < NT; nt++)
#pragma unroll
            for (int i = 0; i < 4; i++) acc[mt][nt][i] = 0.f;

    for (int c = 0; c < NCH; c++) {
        if (c + 1 < NCH) cp_wait<1>(); else cp_wait<0>();
        __syncthreads();
        const float* as = As[c & 1];
        const float* ws = Ws[c & 1];
#pragma unroll
        for (int ks = 0; ks < 4; ks++) {
            int kq = ks * 8 + q;
            uint32_t afr[2][4];
#pragma unroll
            for (int mt = 0; mt < 2; mt++) {
                afr[mt][0] = f2tf(as[(mt * 16 + r)     * PADK + kq]);
                afr[mt][1] = f2tf(as[(mt * 16 + r + 8) * PADK + kq]);
                afr[mt][2] = f2tf(as[(mt * 16 + r)     * PADK + kq + 4]);
                afr[mt][3] = f2tf(as[(mt * 16 + r + 8) * PADK + kq + 4]);
            }
#pragma unroll
            for (int nt = 0; nt < NT; nt++) {
                int n = wid * (NT * 8) + nt * 8 + r;
                uint32_t b0 = f2tf(ws[n * PADK + ks * 8 + q]);
                uint32_t b1 = f2tf(ws[n * PADK + ks * 8 + 4 + q]);
                mma8(acc[0][nt], afr[0], b0, b1);
                mma8(acc[1][nt], afr[1], b0, b1);
            }
        }
        if (c + 2 < NCH) {
            __syncthreads();
            stage_chunk(As[c & 1], Ws[c & 1], A, W, j0, k0 + (c + 2) * 32, NT * 2, tid);
        }
    }
#pragma unroll
    for (int mt = 0; mt < 2; mt++) {
#pragma unroll
        for (int nt = 0; nt < NT; nt++) {
            int col = j0 + wid * (NT * 8) + nt * 8 + 2 * q;
            int row0 = mt * 16 + r;
            float2 v0 = {acc[mt][nt][0], acc[mt][nt][1]};
            float2 v1 = {acc[mt][nt][2], acc[mt][nt][3]};
            if (addend) {
                float2 a0 = *(const float2*)(addend + (size_t)row0 * C + col);
                float2 a1 = *(const float2*)(addend + (size_t)(row0 + 8) * C + col);
                v0.x += a0.x; v0.y += a0.y;
                v1.x += a1.x; v1.y += a1.y;
            }
            *(float2*)(outp + (size_t)row0 * C + col) = v0;
            *(float2*)(outp + (size_t)(row0 + 8) * C + col) = v1;
        }
    }
}

// phase A: dec_proj(8 tiles x4) + gh0(24x4) + gh1(24x4) = 224 blocks
__global__ void __launch_bounds__(128) phaseA_kernel(
        const float* __restrict__ W_att_dec, const float* __restrict__ W_hh) {
    int b = blockIdx.x;
    if (b < 32) {
        int tile = b >> 2, split = b & 3;
        gemm_tc<4, 8>(g_h + NB * HID, W_att_dec, 1024, tile * 128, split * 256,
                      g_dp_part + (size_t)split * NB * 1024, nullptr);
    } else if (b < 128) {
        int x = b - 32; int tile = x >> 2, split = x & 3;
        gemm_tc<4, 8>(g_h, W_hh, G3, tile * 128, split * 256,
                      g_gh0_part + (size_t)split * NB * G3, nullptr);
    } else {
        int x = b - 128; int tile = x >> 2, split = x & 3;
        gemm_tc<4, 8>(g_h + NB * HID, W_hh + (size_t)G3 * 1024, G3, tile * 128,
                      split * 256, g_gh1_part + (size_t)split * NB * G3, nullptr);
    }
}

// merged = ctx @ W_ctx^T + emb_merged[t] : 16 blocks (64-col tiles, full K)
__global__ void __launch_bounds__(128) merged_kernel(
        const float* __restrict__ W_ctx, int t) {
    gemm_tc<2, 32>(g_ctx, W_ctx, 1024, blockIdx.x * 64, 0, g_merged,
                   g_emb_merged + (size_t)t * NB * 1024);
}

// gi: 24 tiles x 4 splits = 96 blocks
__global__ void __launch_bounds__(128) gi_kernel(int layer,
        const float* __restrict__ W_ih) {
    int tile = blockIdx.x >> 2, split = blockIdx.x & 3;
    const float* W = W_ih + (size_t)layer * G3 * 1024;
    const float* A = (layer == 0) ? g_merged : g_h;
    gemm_tc<4, 8>(A, W, G3, tile * 128, split * 256,
                  g_gi_part + (size_t)split * NB * G3, nullptr);
}

// ---------------------------------------------------------------------------
// Prologue GEMM (64x64 tiles, K=1024), fp32 double-buffered
// ---------------------------------------------------------------------------
__global__ void prol_gemm_kernel(int mode,
                                 const float* __restrict__ enc_hids,
                                 const int*   __restrict__ input_ids,
                                 const float* __restrict__ emb_table,
                                 const float* __restrict__ b_in,
                                 const float* __restrict__ b_ctx,
                                 const float* __restrict__ W) {
    __shared__ float As[2][32 * 68];
    __shared__ float Ws[2][32 * 68];
    int b = blockIdx.x;
    int rt = b >> 4, ct = b & 15;
    int r0 = rt * 64, c0 = ct * 64;
    int tid = threadIdx.x;
    int lp = tid & 7, lr = tid >> 3;
    int tx = tid & 15, ty = tid >> 4;
    int rows = (mode == 0) ? 2048 : (TSTEP * NB);

    float4 a[2], wv[2];
#define PROL_FETCH(k0)                                                          \
    {                                                                           \
        _Pragma("unroll")                                                       \
        for (int h = 0; h < 2; h++) {                                           \
            int gr = r0 + lr + h * 32;                                          \
            if (mode == 0) {                                                    \
                a[h] = *(const float4*)(enc_hids + (size_t)gr * 1024 + (k0) + lp * 4); \
            } else if (gr < rows) {                                             \
                int id = input_ids[(gr & 31) * 64 + (gr >> 5)];                 \
                a[h] = *(const float4*)(emb_table + (size_t)id * 1024 + (k0) + lp * 4); \
            } else {                                                            \
                a[h] = make_float4(0.f, 0.f, 0.f, 0.f);                         \
            }                                                                   \
            wv[h] = *(const float4*)(W + (size_t)(c0 + lr + h * 32) * 1024 + (k0) + lp * 4); \
        }                                                                       \
    }
#define PROL_STORE(buf)                                                         \
    {                                                                           \
        _Pragma("unroll")                                                       \
        for (int h = 0; h < 2; h++) {                                           \
            int rr = lr + h * 32;                                               \
            As[buf][(lp * 4 + 0) * 68 + rr] = a[h].x;                           \
            As[buf][(lp * 4 + 1) * 68 + rr] = a[h].y;                           \
            As[buf][(lp * 4 + 2) * 68 + rr] = a[h].z;                           \
            As[buf][(lp * 4 + 3) * 68 + rr] = a[h].w;                           \
            Ws[buf][(lp * 4 + 0) * 68 + rr] = wv[h].x;                          \
            Ws[buf][(lp * 4 + 1) * 68 + rr] = wv[h].y;                          \
            Ws[buf][(lp * 4 + 2) * 68 + rr] = wv[h].z;                          \
            Ws[buf][(lp * 4 + 3) * 68 + rr] = wv[h].w;                          \
        }                                                                       \
    }

    float acc[4][4];
#pragma unroll
    for (int i = 0; i < 4; i++)
#pragma unroll
        for (int j = 0; j < 4; j++) acc[i][j] = 0.f;

    PROL_FETCH(0);
    PROL_STORE(0);
    __syncthreads();
    for (int c = 0; c < 32; c++) {
        const float* as = As[c & 1];
        const float* ws = Ws[c & 1];
        if (c + 1 < 32) PROL_FETCH((c + 1) * 32);
#pragma unroll
        for (int kk = 0; kk < 32; kk++) {
            float4 a4 = *(const float4*)&as[kk * 68 + ty * 4];
            float4 b4 = *(const float4*)&ws[kk * 68 + tx * 4];
            float avv[4] = {a4.x, a4.y, a4.z, a4.w};
            float bvv[4] = {b4.x, b4.y, b4.z, b4.w};
#pragma unroll
            for (int i = 0; i < 4; i++)
#pragma unroll
                for (int j = 0; j < 4; j++) acc[i][j] += avv[i] * bvv[j];
        }
        if (c + 1 < 32) {
            PROL_STORE((c + 1) & 1);
            __syncthreads();
        }
    }
    float* outb = (mode == 0) ? g_enc_proj : g_emb_merged;
#pragma unroll
    for (int i = 0; i < 4; i++) {
        int rr = r0 + ty * 4 + i;
        if (rr >= rows) continue;
#pragma unroll
        for (int j = 0; j < 4; j++) {
            int cc = c0 + tx * 4 + j;
            float bias = (mode == 1) ? (b_in[cc] + b_ctx[cc]) : 0.f;
            outb[(size_t)rr * 1024 + cc] = acc[i][j] + bias;
        }
    }
#undef PROL_FETCH
#undef PROL_STORE
}

// ---------------------------------------------------------------------------
// Attention scores: 256 blocks (n x 8 l-groups), 128 threads
// ---------------------------------------------------------------------------
__device__ float g_score[NB * ENCL];

__global__ void score_kernel(const float* __restrict__ v_att) {
    __shared__ float sdec[1024];
    __shared__ float sv[1024];
    int b = blockIdx.x;
    int n = b >> 3, lg = b & 7;
    int tid = threadIdx.x;
    for (int i = tid; i < 1024; i += 128) {
        sdec[i] = g_dp_part[n * 1024 + i]
                + g_dp_part[(NB + n) * 1024 + i]
                + g_dp_part[(2 * NB + n) * 1024 + i]
                + g_dp_part[(3 * NB + n) * 1024 + i];
        sv[i] = v_att[i];
    }
    __syncthreads();
    int w = tid >> 5, lane = tid & 31;
#pragma unroll
    for (int li = 0; li < 2; li++) {
        int l = lg * 8 + w * 2 + li;
        const float* ep = g_enc_proj + ((size_t)n * 64 + l) * 1024;
        float s = 0.f;
        for (int a = lane; a < 1024; a += 32)
            s += tanh_fast(ep[a] + sdec[a]) * sv[a];
#pragma unroll
        for (int o = 16; o; o >>= 1) s += __shfl_xor_sync(0xffffffffu, s, o);
        if (lane == 0) g_score[n * 64 + l] = s;
    }
}

// softmax + atts out + ctx (32 blocks, 256 threads)
__global__ void softctx_kernel(const float* __restrict__ enc_hids,
                               float* __restrict__ out, int t) {
    __shared__ float satt[64];
    int n = blockIdx.x, tid = threadIdx.x;
    if (tid < 32) {
        float a0 = g_score[n * 64 + tid], a1 = g_score[n * 64 + tid + 32];
        float m = fmaxf(a0, a1);
#pragma unroll
        for (int o = 16; o; o >>= 1) m = fmaxf(m, __shfl_xor_sync(0xffffffffu, m, o));
        float e0 = __expf(a0 - m), e1 = __expf(a1 - m);
        float sum = e0 + e1;
#pragma unroll
        for (int o = 16; o; o >>= 1) sum += __shfl_xor_sync(0xffffffffu, sum, o);
        float inv = 1.f / sum;
        satt[tid]      = e0 * inv;
        satt[tid + 32] = e1 * inv;
        out[ATT_BASE + ((size_t)n * 64 + tid)      * TSTEP + t] = e0 * inv;
        out[ATT_BASE + ((size_t)n * 64 + tid + 32) * TSTEP + t] = e1 * inv;
    }
    __syncthreads();
    int d = tid * 4;
    float4 acc = {0.f, 0.f, 0.f, 0.f};
    const float* eh = enc_hids + (size_t)n * 64 * 1024 + d;
#pragma unroll 8
    for (int l = 0; l < 64; l++) {
        float  al = satt[l];
        float4 e  = *(const float4*)(eh + (size_t)l * 1024);
        acc.x += al * e.x; acc.y += al * e.y; acc.z += al * e.z; acc.w += al * e.w;
    }
    *(float4*)&g_ctx[n * 1024 + d] = acc;
}

// ---------------------------------------------------------------------------
// GRU combine: 4 gi + 4 gh partials + biases
// ---------------------------------------------------------------------------
__device__ __forceinline__ void add4(float* a, float4 v) {
    a[0] += v.x; a[1] += v.y; a[2] += v.z; a[3] += v.w;
}

__global__ void combine_kernel(int layer, int t,
                               const float* __restrict__ b_ih_l,
                               const float* __restrict__ b_hh_l,
                               float* __restrict__ out_hid) {
    int n = blockIdx.x;
    int j = threadIdx.x * 4;
    const float* ghp = layer ? g_gh1_part : g_gh0_part;
    float* h = g_h + (size_t)layer * NB * HID + n * HID;

    float gi[3][4] = {}, gh[3][4] = {};
#pragma unroll
    for (int g = 0; g < 3; g++) {
#pragma unroll
        for (int s = 0; s < 4; s++) {
            add4(gi[g], *(const float4*)(g_gi_part + ((size_t)s * NB + n) * G3 + g * 1024 + j));
            add4(gh[g], *(const float4*)(ghp       + ((size_t)s * NB + n) * G3 + g * 1024 + j));
        }
        add4(gi[g], *(const float4*)(b_ih_l + g * 1024 + j));
        add4(gh[g], *(const float4*)(b_hh_l + g * 1024 + j));
    }
    float4 ho = *(const float4*)(h + j);
    float ho_[4] = {ho.x, ho.y, ho.z, ho.w};
    float hn_[4];
#pragma unroll
    for (int c = 0; c < 4; c++) {
        float r  = 1.f / (1.f + expf(-(gi[0][c] + gh[0][c])));
        float z  = 1.f / (1.f + expf(-(gi[1][c] + gh[1][c])));
        float nn = tanhf(gi[2][c] + r * gh[2][c]);
        hn_[c] = (1.f - z) * nn + z * ho_[c];
    }
    float4 hv = {hn_[0], hn_[1], hn_[2], hn_[3]};
    *(float4*)(h + j) = hv;
    if (out_hid)
        *(float4*)(out_hid + ((size_t)n * TSTEP + t) * 1024 + j) = hv;
}

__global__ void copy_hfinal_kernel(float* __restrict__ out) {
    int i = blockIdx.x * 256 + threadIdx.x;
    out[DECPREV_BASE + i] = g_h[i];
}

// ---------------------------------------------------------------------------
extern "C" void kernel_launch(void* const* d_in, const int* in_sizes, int n_in,
                              void* d_out, int out_size) {
    const int*   input_ids = (const int*)  d_in[0];
    const float* dec_init  = (const float*)d_in[1];
    const float* enc_hids  = (const float*)d_in[2];
    const float* emb_table = (const float*)d_in[3];
    const float* W_in      = (const float*)d_in[4];
    const float* b_in      = (const float*)d_in[5];
    const float* W_ctx     = (const float*)d_in[6];
    const float* b_ctx     = (const float*)d_in[7];
    const float* W_att_dec = (const float*)d_in[8];
    const float* W_att_enc = (const float*)d_in[9];
    const float* v_att     = (const float*)d_in[10];
    const float* W_ih      = (const float*)d_in[11];
    const float* W_hh      = (const float*)d_in[12];
    const float* b_ih      = (const float*)d_in[13];
    const float* b_hh      = (const float*)d_in[14];
    float* out = (float*)d_out;

    init_h_kernel<<<256, 256>>>(dec_init);
    prol_gemm_kernel<<<512, 256>>>(0, enc_hids, input_ids, emb_table, b_in, b_ctx, W_att_enc);
    prol_gemm_kernel<<<512, 256>>>(1, enc_hids, input_ids, emb_table, b_in, b_ctx, W_in);

    for (int t = 0; t < TSTEP; t++) {
        phaseA_kernel<<<224, 128>>>(W_att_dec, W_hh);
        score_kernel<<<256, 128>>>(v_att);
        softctx_kernel<<<32, 256>>>(enc_hids, out, t);
        merged_kernel<<<16, 128>>>(W_ctx, t);
        gi_kernel<<<96, 128>>>(0, W_ih);
        combine_kernel<<<32, 256>>>(0, t, b_ih, b_hh, nullptr);
        gi_kernel<<<96, 128>>>(1, W_ih);
        combine_kernel<<<32, 256>>>(1, t, b_ih + G3, b_hh + G3, out);
    }
    copy_hfinal_kernel<<<256, 256>>>(out);
}